// round 1
// baseline (speedup 1.0000x reference)
#include <cuda_runtime.h>
#include <cuda_bf16.h>

// Problem constants
#define L_DIM 12
#define B_DIM 4
#define H_DIM 12
#define S_DIM 785
#define NP    784            // S-1, LayerNorm width
#define KSC   588            // kth smallest (1-based)
#define NMAPS (L_DIM * H_DIM) // 144 maps per batch
#define NSPLIT 48            // deterministic partial-sum groups
#define MAPS_PER (NMAPS / NSPLIT) // 3

// Deterministic partial column sums: [batch][split][column]
__device__ float g_partial[B_DIM][NSPLIT][NP];

// ---------------------------------------------------------------------------
// Kernel 1: column-sum reduction over (l, h, i>=1) for columns j=1..784.
// Thread-per-column, row-strided loop: consecutive threads hit consecutive
// addresses -> fully coalesced 128B transactions. Pure HBM streaming.
// Grid: (4 column-chunks, NSPLIT, B). Block: 256 threads.
// ---------------------------------------------------------------------------
__global__ __launch_bounds__(256) void colsum_kernel(const float* __restrict__ att)
{
    const int chunk = blockIdx.x;           // 0..3  (256 columns each)
    const int split = blockIdx.y;           // 0..NSPLIT-1
    const int b     = blockIdx.z;           // 0..3
    const int j     = chunk * 256 + threadIdx.x + 1;  // column 1..784
    if (j > NP) return;

    float a0 = 0.f, a1 = 0.f, a2 = 0.f, a3 = 0.f;

    for (int mi = 0; mi < MAPS_PER; ++mi) {
        const int m = split * MAPS_PER + mi;      // 0..143
        const int l = m / H_DIM;
        const int h = m % H_DIM;
        // element offset of att[l][b][h][1][j]
        const float* p = att +
            ((((size_t)l * B_DIM + b) * H_DIM + h) * S_DIM + 1) * (size_t)S_DIM + j;

        // 784 rows, unrolled x8 with 4 accumulators for MLP
        for (int i = 0; i < NP; i += 8) {
            a0 += p[0 * (size_t)S_DIM];
            a1 += p[1 * (size_t)S_DIM];
            a2 += p[2 * (size_t)S_DIM];
            a3 += p[3 * (size_t)S_DIM];
            a0 += p[4 * (size_t)S_DIM];
            a1 += p[5 * (size_t)S_DIM];
            a2 += p[6 * (size_t)S_DIM];
            a3 += p[7 * (size_t)S_DIM];
            p  += 8 * (size_t)S_DIM;
        }
    }
    g_partial[b][split][j - 1] = (a0 + a1) + (a2 + a3);
}

// ---------------------------------------------------------------------------
// Kernel 2: per-batch finalize. Sum the NSPLIT partials (deterministic order),
// two-pass LayerNorm, sigmoid, kth-smallest threshold via O(n^2) rank with
// broadcast shared reads, write the binary mask.
// Grid: B blocks of NP(=784) threads.
// ---------------------------------------------------------------------------
__global__ void finalize_kernel(const float* __restrict__ gamma,
                                const float* __restrict__ beta,
                                float* __restrict__ out)
{
    const int b   = blockIdx.x;
    const int tid = threadIdx.x;            // 0..783

    __shared__ float red[1024];
    __shared__ float sp[NP];
    __shared__ float sh_thr;

    // deterministic reduction over partials
    float s = 0.f;
    #pragma unroll
    for (int q = 0; q < NSPLIT; ++q)
        s += g_partial[b][q][tid];
    s *= (1.0f / (float)NMAPS);             // mean over heads & layers

    // zero the padding once (indices >= NP stay 0 through both reductions:
    // the tree only writes indices < 512)
    if (tid < 1024 - NP) red[NP + tid] = 0.f;

    // --- pass 1: mean ---
    red[tid] = s;
    __syncthreads();
    for (int st = 512; st > 0; st >>= 1) {
        if (tid < st) red[tid] += red[tid + st];
        __syncthreads();
    }
    const float mean = red[0] * (1.0f / (float)NP);
    __syncthreads();

    // --- pass 2: variance ---
    const float d = s - mean;
    red[tid] = d * d;
    __syncthreads();
    for (int st = 512; st > 0; st >>= 1) {
        if (tid < st) red[tid] += red[tid + st];
        __syncthreads();
    }
    const float var = red[0] * (1.0f / (float)NP);

    // LayerNorm + sigmoid
    const float ln = d * rsqrtf(var + 1e-5f) * gamma[tid] + beta[tid];
    const float pv = 1.0f / (1.0f + expf(-ln));
    sp[tid] = pv;
    __syncthreads();

    // rank-based kth smallest: count strictly-less and equal (broadcast LDS)
    int cl = 0, ce = 0;
    for (int i = 0; i < NP; ++i) {
        const float v = sp[i];
        cl += (v <  pv);
        ce += (v == pv);
    }
    // value at sorted position KSC-1 (0-based)
    if (cl <= (KSC - 1) && (KSC - 1) < cl + ce) sh_thr = pv;
    __syncthreads();

    out[b * NP + tid] = (pv > sh_thr) ? 1.0f : 0.0f;
}

// ---------------------------------------------------------------------------
extern "C" void kernel_launch(void* const* d_in, const int* in_sizes, int n_in,
                              void* d_out, int out_size)
{
    const float* att   = (const float*)d_in[0];
    const float* gamma = (const float*)d_in[1];
    const float* beta  = (const float*)d_in[2];
    float* out = (float*)d_out;

    dim3 grid1(4, NSPLIT, B_DIM);
    colsum_kernel<<<grid1, 256>>>(att);
    finalize_kernel<<<B_DIM, NP>>>(gamma, beta, out);
}